// round 6
// baseline (speedup 1.0000x reference)
#include <cuda_runtime.h>
#include <cstdint>

// ---------------------------------------------------------------------------
// Shapes
// ---------------------------------------------------------------------------
#define BT   12
#define CF   1024
#define CQ   128
#define NTOK 2401
#define NP   2432
#define HF   49

// ---------------------------------------------------------------------------
// Scratch
// ---------------------------------------------------------------------------
__device__ float g_X  [(size_t)BT * CF * NP];   // [bt][c][n]
__device__ float g_XT [(size_t)BT * NP * CF];   // [bt][n][c]
__device__ float g_QT [(size_t)BT * NP * CQ];   // [bt][n][o]
__device__ float g_KT [(size_t)BT * NP * CQ];   // [bt][m][o]
__device__ float g_V  [(size_t)BT * CF * NP];   // [bt][c][n]
__device__ float g_ATT[(size_t)BT * NP * NP];   // [bt][n][m]

__device__ __forceinline__ uint32_t f2tf(float f) {
    uint32_t u; asm("cvt.rna.tf32.f32 %0, %1;" : "=r"(u) : "f"(f)); return u;
}

__device__ __forceinline__ void mma_tf32(float c[4], const uint32_t a[4], const uint32_t b[2]) {
    asm volatile(
        "mma.sync.aligned.m16n8k8.row.col.f32.tf32.tf32.f32 "
        "{%0,%1,%2,%3}, {%4,%5,%6,%7}, {%8,%9}, {%0,%1,%2,%3};"
        : "+f"(c[0]), "+f"(c[1]), "+f"(c[2]), "+f"(c[3])
        : "r"(a[0]), "r"(a[1]), "r"(a[2]), "r"(a[3]), "r"(b[0]), "r"(b[1]));
}

// ---------------------------------------------------------------------------
// 1a) X[bt][c][n]  (zero-padded n)
// ---------------------------------------------------------------------------
__global__ void build_x_kernel(const float* __restrict__ img,
                               const float* __restrict__ tac) {
    int n = blockIdx.x * 256 + threadIdx.x;
    int c = blockIdx.y, bt = blockIdx.z;
    if (n >= NP) return;
    float v = 0.0f;
    if (n < NTOK) {
        int i = n / HF, j = n % HF;
        v = (c < 512)
            ? tac[(((size_t)bt * 512 + c) * 7 + (i / 7)) * 7 + (j / 7)]
            : img[(((size_t)bt * 512 + (c - 512)) * 7 + (i % 7)) * 7 + (j % 7)];
    }
    g_X[((size_t)bt * CF + c) * NP + n] = v;
}

// ---------------------------------------------------------------------------
// 1b) XT[bt][n][c]  (zero rows for n >= NTOK)
// ---------------------------------------------------------------------------
__global__ void build_xt_kernel(const float* __restrict__ img,
                                const float* __restrict__ tac) {
    int c = blockIdx.x * 256 + threadIdx.x;
    int n = blockIdx.y, bt = blockIdx.z;
    if (c >= CF) return;
    float v = 0.0f;
    if (n < NTOK) {
        int i = n / HF, j = n % HF;
        v = (c < 512)
            ? tac[(((size_t)bt * 512 + c) * 7 + (i / 7)) * 7 + (j / 7)]
            : img[(((size_t)bt * 512 + (c - 512)) * 7 + (i % 7)) * 7 + (j % 7)];
    }
    g_XT[((size_t)bt * NP + n) * CF + c] = v;
}

// ---------------------------------------------------------------------------
// 2) row softmax (m < 2401), zero padding columns
// ---------------------------------------------------------------------------
__global__ __launch_bounds__(256)
void softmax_kernel() {
    __shared__ float row[NTOK];
    __shared__ float red[256];
    const int n = blockIdx.x, bt = blockIdx.y;
    float* base = g_ATT + ((size_t)bt * NP + n) * NP;
    const int t = threadIdx.x;

    float mx = -1e30f;
    for (int m = t; m < NTOK; m += 256) { float v = base[m]; row[m] = v; mx = fmaxf(mx, v); }
    red[t] = mx; __syncthreads();
    for (int s = 128; s > 0; s >>= 1) { if (t < s) red[t] = fmaxf(red[t], red[t + s]); __syncthreads(); }
    mx = red[0]; __syncthreads();

    float sum = 0.0f;
    for (int m = t; m < NTOK; m += 256) { float e = __expf(row[m] - mx); row[m] = e; sum += e; }
    red[t] = sum; __syncthreads();
    for (int s = 128; s > 0; s >>= 1) { if (t < s) red[t] += red[t + s]; __syncthreads(); }
    float inv = 1.0f / red[0];

    for (int m = t; m < NTOK; m += 256) base[m] = row[m] * inv;
    for (int m = NTOK + t; m < NP; m += 256) base[m] = 0.0f;
}

// ---------------------------------------------------------------------------
// 3) tf32 mma.sync GEMM with k-permuted fragment-friendly smem layout.
//    C[M,N] = A[M,K] @ B[N,K]^T, both operands K-major.
//    Block 128x128, K-chunk 32, 8 warps (2M x 4N), warp tile 64x32.
//    smem row = 32 k-floats in 4 groups of 8, each group permuted
//    {k0,k4,k1,k5,k2,k6,k3,k7}; row stride 40 words (conflict-free v2 loads).
//    SPLIT=1: plain tf32, double-buffered (80 KB)
//    SPLIT=3: 3xTF32 hi/lo, double-buffered (160 KB)
//    EPI 0: C = acc + bias[row]
//    EPI 1: C = gamma*acc + X[row][col], col<NTOK
//    EPI 2: fused q/k projection: blockIdx.y selects (B,bias,C) vs (B2,bias2,C2)
//    EPI 3: C = acc (raw scores)
// ---------------------------------------------------------------------------
#define ROWW 40
#define TILEW (128 * ROWW)           // u32 words per 128x32 tile
#define SMEM1 (4 * TILEW * 4)        // 81920 B
#define SMEM3 (8 * TILEW * 4)        // 163840 B

// Store 16 consecutive k-floats (2 groups) permuted, tf32-rounded.
__device__ __forceinline__ void store_perm_tf32(uint32_t* arr, int sOff, const float4 p[4]) {
    #pragma unroll
    for (int j = 0; j < 2; j++) {
        const float4 lo4 = p[2 * j], hi4 = p[2 * j + 1];
        uint4 u0 = { f2tf(lo4.x), f2tf(hi4.x), f2tf(lo4.y), f2tf(hi4.y) };
        uint4 u1 = { f2tf(lo4.z), f2tf(hi4.z), f2tf(lo4.w), f2tf(hi4.w) };
        *reinterpret_cast<uint4*>(&arr[sOff + j * 8])     = u0;
        *reinterpret_cast<uint4*>(&arr[sOff + j * 8 + 4]) = u1;
    }
}

// Split hi/lo store (3xTF32).
__device__ __forceinline__ void store_perm_split(uint32_t* hiA, uint32_t* loA,
                                                 int sOff, const float4 p[4]) {
    #pragma unroll
    for (int j = 0; j < 2; j++) {
        const float4 a = p[2 * j], b = p[2 * j + 1];
        uint32_t h0 = f2tf(a.x), h1 = f2tf(a.y), h2 = f2tf(a.z), h3 = f2tf(a.w);
        uint32_t h4 = f2tf(b.x), h5 = f2tf(b.y), h6 = f2tf(b.z), h7 = f2tf(b.w);
        uint4 uh0 = { h0, h4, h1, h5 };
        uint4 uh1 = { h2, h6, h3, h7 };
        uint4 ul0 = { f2tf(a.x - __uint_as_float(h0)), f2tf(b.x - __uint_as_float(h4)),
                      f2tf(a.y - __uint_as_float(h1)), f2tf(b.y - __uint_as_float(h5)) };
        uint4 ul1 = { f2tf(a.z - __uint_as_float(h2)), f2tf(b.z - __uint_as_float(h6)),
                      f2tf(a.w - __uint_as_float(h3)), f2tf(b.w - __uint_as_float(h7)) };
        *reinterpret_cast<uint4*>(&hiA[sOff + j * 8])     = uh0;
        *reinterpret_cast<uint4*>(&hiA[sOff + j * 8 + 4]) = uh1;
        *reinterpret_cast<uint4*>(&loA[sOff + j * 8])     = ul0;
        *reinterpret_cast<uint4*>(&loA[sOff + j * 8 + 4]) = ul1;
    }
}

template <int EPI, int SPLIT>
__global__ __launch_bounds__(256, 1)
void gemm_mma_kernel(const float* __restrict__ A, int lda, size_t strideA,
                     const float* __restrict__ B, int ldb, size_t strideB,
                     const float* __restrict__ B2,
                     int K,
                     const float* __restrict__ bias,
                     const float* __restrict__ bias2,
                     const float* __restrict__ gamma,
                     const float* __restrict__ Xres,
                     float* __restrict__ C, int ldc, size_t strideC,
                     float* __restrict__ C2) {
    extern __shared__ uint32_t sm[];

    const int bt = blockIdx.z;
    const int m0 = blockIdx.x * 128;
    int n0;
    const float* Bsel;
    const float* biassel;
    float* Csel;
    if (EPI == 2) {
        n0 = 0;
        const bool alt = (blockIdx.y != 0);
        Bsel = alt ? B2 : B;
        biassel = alt ? bias2 : bias;
        Csel = alt ? C2 : C;
    } else {
        n0 = blockIdx.y * 128;
        Bsel = B; biassel = bias; Csel = C;
    }

    const float* Ab = A + (size_t)bt * strideA + (size_t)m0 * lda;
    const float* Bb = Bsel + (size_t)bt * strideB + (size_t)n0 * ldb;

    const int t = threadIdx.x;
    const int wid = t >> 5, lane = t & 31;
    const int warp_m = wid & 1, warp_n = wid >> 1;
    const int l4 = lane >> 2, lm = lane & 3;

    // producer mapping: 2 threads per row, 16 consecutive k-floats each
    const int prow = t >> 1;
    const int pcol = (t & 1) * 16;                  // also the word offset (2 groups)
    const float* aRow = Ab + (size_t)prow * lda + pcol;
    const float* bRow = Bb + (size_t)prow * ldb + pcol;
    const int sOff = prow * ROWW + pcol;

    float acc[4][4][4];
    #pragma unroll
    for (int mi = 0; mi < 4; mi++)
        #pragma unroll
        for (int ni = 0; ni < 4; ni++)
            #pragma unroll
            for (int r = 0; r < 4; r++) acc[mi][ni][r] = 0.0f;

    const int NCH = K / 32;
    float4 pa[4], pb[4];
    #pragma unroll
    for (int q = 0; q < 4; q++) {
        pa[q] = *reinterpret_cast<const float4*>(aRow + q * 4);
        pb[q] = *reinterpret_cast<const float4*>(bRow + q * 4);
    }

    if (SPLIT == 1) {
        uint32_t* Abuf[2] = { sm,         sm + 2 * TILEW };
        uint32_t* Bbuf[2] = { sm + TILEW, sm + 3 * TILEW };
        store_perm_tf32(Abuf[0], sOff, pa);
        store_perm_tf32(Bbuf[0], sOff, pb);
        __syncthreads();

        for (int ch = 0; ch < NCH; ch++) {
            const int buf = ch & 1;
            if (ch + 1 < NCH) {
                const int k1 = (ch + 1) * 32;
                #pragma unroll
                for (int q = 0; q < 4; q++) {
                    pa[q] = *reinterpret_cast<const float4*>(aRow + k1 + q * 4);
                    pb[q] = *reinterpret_cast<const float4*>(bRow + k1 + q * 4);
                }
            }
            const uint32_t* as = Abuf[buf];
            const uint32_t* bs = Bbuf[buf];
            #pragma unroll
            for (int g = 0; g < 4; g++) {
                const int kb = g * 8 + 2 * lm;
                uint32_t b[4][2];
                #pragma unroll
                for (int ni = 0; ni < 4; ni++) {
                    uint2 bb = *reinterpret_cast<const uint2*>(
                        &bs[(warp_n * 32 + ni * 8 + l4) * ROWW + kb]);
                    b[ni][0] = bb.x; b[ni][1] = bb.y;
                }
                #pragma unroll
                for (int mi = 0; mi < 4; mi++) {
                    const int ro = (warp_m * 64 + mi * 16 + l4) * ROWW + kb;
                    uint2 A0 = *reinterpret_cast<const uint2*>(&as[ro]);
                    uint2 A8 = *reinterpret_cast<const uint2*>(&as[ro + 8 * ROWW]);
                    uint32_t a[4] = { A0.x, A8.x, A0.y, A8.y };
                    #pragma unroll
                    for (int ni = 0; ni < 4; ni++) mma_tf32(acc[mi][ni], a, b[ni]);
                }
            }
            if (ch + 1 < NCH) {
                store_perm_tf32(Abuf[buf ^ 1], sOff, pa);
                store_perm_tf32(Bbuf[buf ^ 1], sOff, pb);
            }
            __syncthreads();
        }
    } else {
        // SPLIT == 3: hi/lo, double-buffered
        uint32_t* base[2] = { sm, sm + 4 * TILEW };
        store_perm_split(base[0], base[0] + 2 * TILEW, sOff, pa);              // Ahi, Alo
        store_perm_split(base[0] + TILEW, base[0] + 3 * TILEW, sOff, pb);      // Bhi, Blo
        __syncthreads();

        for (int ch = 0; ch < NCH; ch++) {
            const int buf = ch & 1;
            if (ch + 1 < NCH) {
                const int k1 = (ch + 1) * 32;
                #pragma unroll
                for (int q = 0; q < 4; q++) {
                    pa[q] = *reinterpret_cast<const float4*>(aRow + k1 + q * 4);
                    pb[q] = *reinterpret_cast<const float4*>(bRow + k1 + q * 4);
                }
            }
            const uint32_t* Ahi = base[buf];
            const uint32_t* Bhi = base[buf] + TILEW;
            const uint32_t* Alo = base[buf] + 2 * TILEW;
            const uint32_t* Blo = base[buf] + 3 * TILEW;
            #pragma unroll
            for (int g = 0; g < 4; g++) {
                const int kb = g * 8 + 2 * lm;
                uint32_t bh[4][2], bl[4][2];
                #pragma unroll
                for (int ni = 0; ni < 4; ni++) {
                    const int ro = (warp_n * 32 + ni * 8 + l4) * ROWW + kb;
                    uint2 hh = *reinterpret_cast<const uint2*>(&Bhi[ro]);
                    uint2 ll = *reinterpret_cast<const uint2*>(&Blo[ro]);
                    bh[ni][0] = hh.x; bh[ni][1] = hh.y;
                    bl[ni][0] = ll.x; bl[ni][1] = ll.y;
                }
                #pragma unroll
                for (int mi = 0; mi < 4; mi++) {
                    const int ro = (warp_m * 64 + mi * 16 + l4) * ROWW + kb;
                    uint2 H0 = *reinterpret_cast<const uint2*>(&Ahi[ro]);
                    uint2 H8 = *reinterpret_cast<const uint2*>(&Ahi[ro + 8 * ROWW]);
                    uint2 L0 = *reinterpret_cast<const uint2*>(&Alo[ro]);
                    uint2 L8 = *reinterpret_cast<const uint2*>(&Alo[ro + 8 * ROWW]);
                    uint32_t ah[4] = { H0.x, H8.x, H0.y, H8.y };
                    uint32_t al[4] = { L0.x, L8.x, L0.y, L8.y };
                    #pragma unroll
                    for (int ni = 0; ni < 4; ni++) {
                        mma_tf32(acc[mi][ni], ah, bl[ni]);
                        mma_tf32(acc[mi][ni], al, bh[ni]);
                        mma_tf32(acc[mi][ni], ah, bh[ni]);
                    }
                }
            }
            if (ch + 1 < NCH) {
                store_perm_split(base[buf ^ 1], base[buf ^ 1] + 2 * TILEW, sOff, pa);
                store_perm_split(base[buf ^ 1] + TILEW, base[buf ^ 1] + 3 * TILEW, sOff, pb);
            }
            __syncthreads();
        }
    }

    // ------------------------- epilogues -------------------------
    float* Cb = Csel + (size_t)bt * strideC;
    if (EPI == 0) {
        #pragma unroll
        for (int mi = 0; mi < 4; mi++) {
            const int gr = m0 + warp_m * 64 + mi * 16 + l4;
            const float bv0 = biassel[gr], bv8 = biassel[gr + 8];
            #pragma unroll
            for (int ni = 0; ni < 4; ni++) {
                const int gc = n0 + warp_n * 32 + ni * 8 + lm * 2;
                float2 o0 = { acc[mi][ni][0] + bv0, acc[mi][ni][1] + bv0 };
                float2 o1 = { acc[mi][ni][2] + bv8, acc[mi][ni][3] + bv8 };
                *reinterpret_cast<float2*>(&Cb[(size_t)gr * ldc + gc]) = o0;
                *reinterpret_cast<float2*>(&Cb[(size_t)(gr + 8) * ldc + gc]) = o1;
            }
        }
    } else if (EPI == 1) {
        const float g = __ldg(gamma);
        const float* Xb = Xres + (size_t)bt * CF * NP;
        #pragma unroll
        for (int mi = 0; mi < 4; mi++) {
            const int gr = m0 + warp_m * 64 + mi * 16 + l4;
            #pragma unroll
            for (int ni = 0; ni < 4; ni++) {
                const int gc = n0 + warp_n * 32 + ni * 8 + lm * 2;
                if (gc < NTOK)
                    Cb[(size_t)gr * ldc + gc] = g * acc[mi][ni][0] + Xb[(size_t)gr * NP + gc];
                if (gc + 1 < NTOK)
                    Cb[(size_t)gr * ldc + gc + 1] = g * acc[mi][ni][1] + Xb[(size_t)gr * NP + gc + 1];
                if (gc < NTOK)
                    Cb[(size_t)(gr + 8) * ldc + gc] = g * acc[mi][ni][2] + Xb[(size_t)(gr + 8) * NP + gc];
                if (gc + 1 < NTOK)
                    Cb[(size_t)(gr + 8) * ldc + gc + 1] = g * acc[mi][ni][3] + Xb[(size_t)(gr + 8) * NP + gc + 1];
            }
        }
    } else if (EPI == 2) {
        #pragma unroll
        for (int mi = 0; mi < 4; mi++) {
            const int gr = m0 + warp_m * 64 + mi * 16 + l4;
            #pragma unroll
            for (int ni = 0; ni < 4; ni++) {
                const int gc = n0 + warp_n * 32 + ni * 8 + lm * 2;
                const float b0 = biassel[gc], b1 = biassel[gc + 1];
                float2 o0 = { acc[mi][ni][0] + b0, acc[mi][ni][1] + b1 };
                float2 o1 = { acc[mi][ni][2] + b0, acc[mi][ni][3] + b1 };
                *reinterpret_cast<float2*>(&Cb[(size_t)gr * ldc + gc]) = o0;
                *reinterpret_cast<float2*>(&Cb[(size_t)(gr + 8) * ldc + gc]) = o1;
            }
        }
    } else {
        #pragma unroll
        for (int mi = 0; mi < 4; mi++) {
            const int gr = m0 + warp_m * 64 + mi * 16 + l4;
            #pragma unroll
            for (int ni = 0; ni < 4; ni++) {
                const int gc = n0 + warp_n * 32 + ni * 8 + lm * 2;
                float2 o0 = { acc[mi][ni][0], acc[mi][ni][1] };
                float2 o1 = { acc[mi][ni][2], acc[mi][ni][3] };
                *reinterpret_cast<float2*>(&Cb[(size_t)gr * ldc + gc]) = o0;
                *reinterpret_cast<float2*>(&Cb[(size_t)(gr + 8) * ldc + gc]) = o1;
            }
        }
    }
}

// ---------------------------------------------------------------------------
// Launch
// ---------------------------------------------------------------------------
extern "C" void kernel_launch(void* const* d_in, const int* in_sizes, int n_in,
                              void* d_out, int out_size) {
    const float* img   = (const float*)d_in[0];
    const float* tac   = (const float*)d_in[1];
    const float* Wq    = (const float*)d_in[2];
    const float* bq    = (const float*)d_in[3];
    const float* Wk    = (const float*)d_in[4];
    const float* bk    = (const float*)d_in[5];
    const float* Wv    = (const float*)d_in[6];
    const float* bv    = (const float*)d_in[7];
    const float* gamma = (const float*)d_in[8];
    float* out = (float*)d_out;

    float* gX;  cudaGetSymbolAddress((void**)&gX,  g_X);
    float* gXT; cudaGetSymbolAddress((void**)&gXT, g_XT);
    float* gQT; cudaGetSymbolAddress((void**)&gQT, g_QT);
    float* gKT; cudaGetSymbolAddress((void**)&gKT, g_KT);
    float* gV;  cudaGetSymbolAddress((void**)&gV,  g_V);
    float* gA;  cudaGetSymbolAddress((void**)&gA,  g_ATT);

    cudaFuncSetAttribute(gemm_mma_kernel<0,1>, cudaFuncAttributeMaxDynamicSharedMemorySize, SMEM1);
    cudaFuncSetAttribute(gemm_mma_kernel<1,1>, cudaFuncAttributeMaxDynamicSharedMemorySize, SMEM1);
    cudaFuncSetAttribute(gemm_mma_kernel<2,3>, cudaFuncAttributeMaxDynamicSharedMemorySize, SMEM3);
    cudaFuncSetAttribute(gemm_mma_kernel<3,3>, cudaFuncAttributeMaxDynamicSharedMemorySize, SMEM3);

    // 1) fused feature maps
    build_x_kernel <<<dim3((NP + 255) / 256, CF, BT), 256>>>(img, tac);
    build_xt_kernel<<<dim3(CF / 256, NP, BT), 256>>>(img, tac);

    // 2) fused q+k projections (3xTF32): QT/KT[n][o] = XT[n][:] @ W^T + b
    gemm_mma_kernel<2,3><<<dim3(NP / 128, 2, BT), 256, SMEM3>>>(
        gXT, CF, (size_t)NP * CF,
        Wq, CF, 0, Wk,
        CF, bq, bk, nullptr, nullptr,
        gQT, CQ, (size_t)NP * CQ, gKT);

    // 3) v projection (tf32): V[c][n] = Wv @ XT^T + bv
    gemm_mma_kernel<0,1><<<dim3(CF / 128, NP / 128, BT), 256, SMEM1>>>(
        Wv, CF, 0,
        gXT, CF, (size_t)NP * CF, nullptr,
        CF, bv, nullptr, nullptr, nullptr,
        gV, NP, (size_t)CF * NP, nullptr);

    // 4) attention scores (3xTF32): S[n][m] = QT[n][:] @ KT[m][:]^T
    gemm_mma_kernel<3,3><<<dim3(NP / 128, NP / 128, BT), 256, SMEM3>>>(
        gQT, CQ, (size_t)NP * CQ,
        gKT, CQ, (size_t)NP * CQ, nullptr,
        CQ, nullptr, nullptr, nullptr, nullptr,
        gA, NP, (size_t)NP * NP, nullptr);

    // 5) softmax
    softmax_kernel<<<dim3(NTOK, BT), 256>>>();

    // 6) out = gamma * (V @ P^T) + X (tf32)
    gemm_mma_kernel<1,1><<<dim3(CF / 128, NP / 128, BT), 256, SMEM1>>>(
        gV, NP, (size_t)CF * NP,
        gA, NP, (size_t)NP * NP, nullptr,
        NP, nullptr, nullptr, gamma, gX,
        out, NTOK, (size_t)CF * NTOK, nullptr);
}

// round 7
// speedup vs baseline: 1.2202x; 1.2202x over previous
#include <cuda_runtime.h>
#include <cstdint>

// ---------------------------------------------------------------------------
// Shapes
// ---------------------------------------------------------------------------
#define BT   12
#define CF   1024
#define CQ   128
#define NTOK 2401
#define NP   2432
#define HF   49

// ---------------------------------------------------------------------------
// Scratch
// ---------------------------------------------------------------------------
__device__ float g_X  [(size_t)BT * CF * NP];   // [bt][c][n]
__device__ float g_XT [(size_t)BT * NP * CF];   // [bt][n][c]
__device__ float g_QT [(size_t)BT * NP * CQ];   // [bt][n][o]
__device__ float g_KT [(size_t)BT * NP * CQ];   // [bt][m][o]
__device__ float g_V  [(size_t)BT * CF * NP];   // [bt][c][n]
__device__ float g_ATT[(size_t)BT * NP * NP];   // [bt][n][m]

__device__ __forceinline__ uint32_t f2tf(float f) {
    uint32_t u; asm("cvt.rna.tf32.f32 %0, %1;" : "=r"(u) : "f"(f)); return u;
}
__device__ __forceinline__ uint32_t u2tf(uint32_t x) {
    uint32_t u; asm("cvt.rna.tf32.f32 %0, %1;" : "=r"(u) : "f"(__uint_as_float(x))); return u;
}
__device__ __forceinline__ uint32_t smem_u32(const void* p) {
    uint32_t a;
    asm("{ .reg .u64 t; cvta.to.shared.u64 t, %1; cvt.u32.u64 %0, t; }" : "=r"(a) : "l"(p));
    return a;
}

__device__ __forceinline__ void mma_tf32(float c[4], const uint32_t a[4], const uint32_t b[2]) {
    asm volatile(
        "mma.sync.aligned.m16n8k8.row.col.f32.tf32.tf32.f32 "
        "{%0,%1,%2,%3}, {%4,%5,%6,%7}, {%8,%9}, {%0,%1,%2,%3};"
        : "+f"(c[0]), "+f"(c[1]), "+f"(c[2]), "+f"(c[3])
        : "r"(a[0]), "r"(a[1]), "r"(a[2]), "r"(a[3]), "r"(b[0]), "r"(b[1]));
}

#define CP_ASYNC16(dst_u32, src_ptr) \
    asm volatile("cp.async.cg.shared.global [%0], [%1], 16;" :: "r"(dst_u32), "l"(src_ptr) : "memory")
#define CP_COMMIT() asm volatile("cp.async.commit_group;" ::: "memory")
#define CP_WAIT0()  asm volatile("cp.async.wait_group 0;" ::: "memory")
#define CP_WAIT1()  asm volatile("cp.async.wait_group 1;" ::: "memory")

// ---------------------------------------------------------------------------
// 1a) X[bt][c][n]  (zero-padded n)
// ---------------------------------------------------------------------------
__global__ void build_x_kernel(const float* __restrict__ img,
                               const float* __restrict__ tac) {
    int n = blockIdx.x * 256 + threadIdx.x;
    int c = blockIdx.y, bt = blockIdx.z;
    if (n >= NP) return;
    float v = 0.0f;
    if (n < NTOK) {
        int i = n / HF, j = n % HF;
        v = (c < 512)
            ? tac[(((size_t)bt * 512 + c) * 7 + (i / 7)) * 7 + (j / 7)]
            : img[(((size_t)bt * 512 + (c - 512)) * 7 + (i % 7)) * 7 + (j % 7)];
    }
    g_X[((size_t)bt * CF + c) * NP + n] = v;
}

// ---------------------------------------------------------------------------
// 1b) XT[bt][n][c]  (zero rows for n >= NTOK)
// ---------------------------------------------------------------------------
__global__ void build_xt_kernel(const float* __restrict__ img,
                                const float* __restrict__ tac) {
    int c = blockIdx.x * 256 + threadIdx.x;
    int n = blockIdx.y, bt = blockIdx.z;
    if (c >= CF) return;
    float v = 0.0f;
    if (n < NTOK) {
        int i = n / HF, j = n % HF;
        v = (c < 512)
            ? tac[(((size_t)bt * 512 + c) * 7 + (i / 7)) * 7 + (j / 7)]
            : img[(((size_t)bt * 512 + (c - 512)) * 7 + (i % 7)) * 7 + (j % 7)];
    }
    g_XT[((size_t)bt * NP + n) * CF + c] = v;
}

// ---------------------------------------------------------------------------
// 2) row softmax (m < 2401), zero padding columns
// ---------------------------------------------------------------------------
__global__ __launch_bounds__(256)
void softmax_kernel() {
    __shared__ float row[NTOK];
    __shared__ float red[256];
    const int n = blockIdx.x, bt = blockIdx.y;
    float* base = g_ATT + ((size_t)bt * NP + n) * NP;
    const int t = threadIdx.x;

    float mx = -1e30f;
    for (int m = t; m < NTOK; m += 256) { float v = base[m]; row[m] = v; mx = fmaxf(mx, v); }
    red[t] = mx; __syncthreads();
    for (int s = 128; s > 0; s >>= 1) { if (t < s) red[t] = fmaxf(red[t], red[t + s]); __syncthreads(); }
    mx = red[0]; __syncthreads();

    float sum = 0.0f;
    for (int m = t; m < NTOK; m += 256) { float e = __expf(row[m] - mx); row[m] = e; sum += e; }
    red[t] = sum; __syncthreads();
    for (int s = 128; s > 0; s >>= 1) { if (t < s) red[t] += red[t + s]; __syncthreads(); }
    float inv = 1.0f / red[0];

    for (int m = t; m < NTOK; m += 256) base[m] = row[m] * inv;
    for (int m = NTOK + t; m < NP; m += 256) base[m] = 0.0f;
}

// ---------------------------------------------------------------------------
// Shared tiling constants (stride-36 layout, conflict-free scalar LDS)
// ---------------------------------------------------------------------------
#define LDS_S 36
#define TILEW (128 * LDS_S)            // words per 128x32 tile
#define SMEM_T (4 * TILEW * 4)         // 73728 B (either 2 bufs x (A+B) or hi/lo x (A+B))

// ---------------------------------------------------------------------------
// 3) SPLIT=1 tf32 GEMM, cp.async double-buffered, 2 CTAs/SM target.
//    C[M,N] = A[M,K] @ B[N,K]^T (both K-major). Raw fp32 staged in smem;
//    consumer applies cvt.rna.tf32 on fragments.
//    EPI 0: C = acc + bias[row]
//    EPI 1: C = gamma*acc + X[row][col], col<NTOK
// ---------------------------------------------------------------------------
template <int EPI>
__global__ __launch_bounds__(256, 2)
void gemm_async_kernel(const float* __restrict__ A, int lda, size_t strideA,
                       const float* __restrict__ B, int ldb, size_t strideB,
                       int K,
                       const float* __restrict__ bias,
                       const float* __restrict__ gamma,
                       const float* __restrict__ Xres,
                       float* __restrict__ C, int ldc, size_t strideC) {
    extern __shared__ uint32_t sm[];
    // layout: A0 @0, B0 @TILEW, A1 @2*TILEW, B1 @3*TILEW
    const uint32_t smem_base = smem_u32(sm);

    const int bt = blockIdx.z;
    const int m0 = blockIdx.x * 128;
    const int n0 = blockIdx.y * 128;
    const float* Ab = A + (size_t)bt * strideA + (size_t)m0 * lda;
    const float* Bb = B + (size_t)bt * strideB + (size_t)n0 * ldb;

    const int t = threadIdx.x;
    const int wid = t >> 5, lane = t & 31;
    const int warp_m = wid & 1, warp_n = wid >> 1;
    const int l4 = lane >> 2, lm = lane & 3;

    // producer mapping: 2 threads per row, 16 consecutive floats (4 x 16B)
    const int prow = t >> 1;
    const int pcol = (t & 1) * 16;
    const float* aRow = Ab + (size_t)prow * lda + pcol;
    const float* bRow = Bb + (size_t)prow * ldb + pcol;
    const uint32_t sA0 = smem_base + (prow * LDS_S + pcol) * 4;
    const uint32_t sB0 = sA0 + TILEW * 4;

    float acc[4][4][4];
    #pragma unroll
    for (int mi = 0; mi < 4; mi++)
        #pragma unroll
        for (int ni = 0; ni < 4; ni++)
            #pragma unroll
            for (int r = 0; r < 4; r++) acc[mi][ni][r] = 0.0f;

    const int NCH = K / 32;

    // prologue: issue chunk 0 into buffer 0
    #pragma unroll
    for (int q = 0; q < 4; q++) {
        CP_ASYNC16(sA0 + q * 16, aRow + q * 4);
        CP_ASYNC16(sB0 + q * 16, bRow + q * 4);
    }
    CP_COMMIT();

    for (int ch = 0; ch < NCH; ch++) {
        const int buf = ch & 1;
        if (ch + 1 < NCH) {
            const int k1 = (ch + 1) * 32;
            const uint32_t dA = sA0 + (buf ^ 1) * (2 * TILEW * 4);
            const uint32_t dB = sB0 + (buf ^ 1) * (2 * TILEW * 4);
            #pragma unroll
            for (int q = 0; q < 4; q++) {
                CP_ASYNC16(dA + q * 16, aRow + k1 + q * 4);
                CP_ASYNC16(dB + q * 16, bRow + k1 + q * 4);
            }
            CP_COMMIT();
            CP_WAIT1();
        } else {
            CP_WAIT0();
        }
        __syncthreads();

        const uint32_t* as = sm + buf * 2 * TILEW;
        const uint32_t* bs = as + TILEW;
        #pragma unroll
        for (int g = 0; g < 4; g++) {
            const int kk = g * 8;
            uint32_t b[4][2];
            #pragma unroll
            for (int ni = 0; ni < 4; ni++) {
                const int base = (warp_n * 32 + ni * 8 + l4) * LDS_S + kk + lm;
                b[ni][0] = u2tf(bs[base]);
                b[ni][1] = u2tf(bs[base + 4]);
            }
            #pragma unroll
            for (int mi = 0; mi < 4; mi++) {
                const int base = (warp_m * 64 + mi * 16 + l4) * LDS_S + kk + lm;
                uint32_t a[4];
                a[0] = u2tf(as[base]);
                a[1] = u2tf(as[base + 8 * LDS_S]);
                a[2] = u2tf(as[base + 4]);
                a[3] = u2tf(as[base + 8 * LDS_S + 4]);
                #pragma unroll
                for (int ni = 0; ni < 4; ni++) mma_tf32(acc[mi][ni], a, b[ni]);
            }
        }
        __syncthreads();
    }

    // ------------------------- epilogues -------------------------
    float* Cb = C + (size_t)bt * strideC;
    if (EPI == 0) {
        #pragma unroll
        for (int mi = 0; mi < 4; mi++) {
            const int gr = m0 + warp_m * 64 + mi * 16 + l4;
            const float bv0 = bias[gr], bv8 = bias[gr + 8];
            #pragma unroll
            for (int ni = 0; ni < 4; ni++) {
                const int gc = n0 + warp_n * 32 + ni * 8 + lm * 2;
                float2 o0 = { acc[mi][ni][0] + bv0, acc[mi][ni][1] + bv0 };
                float2 o1 = { acc[mi][ni][2] + bv8, acc[mi][ni][3] + bv8 };
                *reinterpret_cast<float2*>(&Cb[(size_t)gr * ldc + gc]) = o0;
                *reinterpret_cast<float2*>(&Cb[(size_t)(gr + 8) * ldc + gc]) = o1;
            }
        }
    } else {
        const float g = __ldg(gamma);
        const float* Xb = Xres + (size_t)bt * CF * NP;
        #pragma unroll
        for (int mi = 0; mi < 4; mi++) {
            const int gr = m0 + warp_m * 64 + mi * 16 + l4;
            #pragma unroll
            for (int ni = 0; ni < 4; ni++) {
                const int gc = n0 + warp_n * 32 + ni * 8 + lm * 2;
                if (gc < NTOK)
                    Cb[(size_t)gr * ldc + gc] = g * acc[mi][ni][0] + Xb[(size_t)gr * NP + gc];
                if (gc + 1 < NTOK)
                    Cb[(size_t)gr * ldc + gc + 1] = g * acc[mi][ni][1] + Xb[(size_t)gr * NP + gc + 1];
                if (gc < NTOK)
                    Cb[(size_t)(gr + 8) * ldc + gc] = g * acc[mi][ni][2] + Xb[(size_t)(gr + 8) * NP + gc];
                if (gc + 1 < NTOK)
                    Cb[(size_t)(gr + 8) * ldc + gc + 1] = g * acc[mi][ni][3] + Xb[(size_t)(gr + 8) * NP + gc + 1];
            }
        }
    }
}

// ---------------------------------------------------------------------------
// 4) SPLIT=3 (3xTF32) GEMM — R5-proven form: stride-36, single-buffered,
//    register prefetch. EPI 2: C = acc + bias[col]; EPI 3: C = acc.
// ---------------------------------------------------------------------------
template <int EPI>
__global__ __launch_bounds__(256, 1)
void gemm_mma3_kernel(const float* __restrict__ A, int lda, size_t strideA,
                      const float* __restrict__ B, int ldb, size_t strideB,
                      int K,
                      const float* __restrict__ bias,
                      float* __restrict__ C, int ldc, size_t strideC) {
    extern __shared__ uint32_t sm[];
    uint32_t* Ahi = sm;
    uint32_t* Bhi = sm + TILEW;
    uint32_t* Alo = sm + 2 * TILEW;
    uint32_t* Blo = sm + 3 * TILEW;

    const int bt = blockIdx.z;
    const int m0 = blockIdx.x * 128;
    const int n0 = blockIdx.y * 128;
    const float* Ab = A + (size_t)bt * strideA + (size_t)m0 * lda;
    const float* Bb = B + (size_t)bt * strideB + (size_t)n0 * ldb;

    const int t = threadIdx.x;
    const int wid = t >> 5, lane = t & 31;
    const int warp_m = wid & 1, warp_n = wid >> 1;
    const int l4 = lane >> 2, lm = lane & 3;

    const int prow = t >> 1;
    const int pcol = (t & 1) * 16;
    const float* aRow = Ab + (size_t)prow * lda + pcol;
    const float* bRow = Bb + (size_t)prow * ldb + pcol;
    const int sOff = prow * LDS_S + pcol;

    float acc[4][4][4];
    #pragma unroll
    for (int mi = 0; mi < 4; mi++)
        #pragma unroll
        for (int ni = 0; ni < 4; ni++)
            #pragma unroll
            for (int r = 0; r < 4; r++) acc[mi][ni][r] = 0.0f;

    const int NCH = K / 32;
    float4 pa[4], pb[4];
    #pragma unroll
    for (int q = 0; q < 4; q++) {
        pa[q] = *reinterpret_cast<const float4*>(aRow + q * 4);
        pb[q] = *reinterpret_cast<const float4*>(bRow + q * 4);
    }

    for (int ch = 0; ch < NCH; ch++) {
        #pragma unroll
        for (int q = 0; q < 4; q++) {
            uint32_t hx = f2tf(pa[q].x), hy = f2tf(pa[q].y),
                     hz = f2tf(pa[q].z), hw = f2tf(pa[q].w);
            uint4 uh = { hx, hy, hz, hw };
            uint4 ul = { f2tf(pa[q].x - __uint_as_float(hx)),
                         f2tf(pa[q].y - __uint_as_float(hy)),
                         f2tf(pa[q].z - __uint_as_float(hz)),
                         f2tf(pa[q].w - __uint_as_float(hw)) };
            *reinterpret_cast<uint4*>(&Ahi[sOff + q * 4]) = uh;
            *reinterpret_cast<uint4*>(&Alo[sOff + q * 4]) = ul;
            hx = f2tf(pb[q].x); hy = f2tf(pb[q].y);
            hz = f2tf(pb[q].z); hw = f2tf(pb[q].w);
            uint4 vh = { hx, hy, hz, hw };
            uint4 vl = { f2tf(pb[q].x - __uint_as_float(hx)),
                         f2tf(pb[q].y - __uint_as_float(hy)),
                         f2tf(pb[q].z - __uint_as_float(hz)),
                         f2tf(pb[q].w - __uint_as_float(hw)) };
            *reinterpret_cast<uint4*>(&Bhi[sOff + q * 4]) = vh;
            *reinterpret_cast<uint4*>(&Blo[sOff + q * 4]) = vl;
        }
        __syncthreads();
        if (ch + 1 < NCH) {
            const int k1 = (ch + 1) * 32;
            #pragma unroll
            for (int q = 0; q < 4; q++) {
                pa[q] = *reinterpret_cast<const float4*>(aRow + k1 + q * 4);
                pb[q] = *reinterpret_cast<const float4*>(bRow + k1 + q * 4);
            }
        }
        #pragma unroll
        for (int g = 0; g < 4; g++) {
            const int kk = g * 8;
            uint32_t bh[4][2], bl[4][2];
            #pragma unroll
            for (int ni = 0; ni < 4; ni++) {
                const int base = (warp_n * 32 + ni * 8 + l4) * LDS_S + kk + lm;
                bh[ni][0] = Bhi[base];  bh[ni][1] = Bhi[base + 4];
                bl[ni][0] = Blo[base];  bl[ni][1] = Blo[base + 4];
            }
            #pragma unroll
            for (int mi = 0; mi < 4; mi++) {
                const int base = (warp_m * 64 + mi * 16 + l4) * LDS_S + kk + lm;
                uint32_t ah[4], al[4];
                ah[0] = Ahi[base];                 al[0] = Alo[base];
                ah[1] = Ahi[base + 8 * LDS_S];     al[1] = Alo[base + 8 * LDS_S];
                ah[2] = Ahi[base + 4];             al[2] = Alo[base + 4];
                ah[3] = Ahi[base + 8 * LDS_S + 4]; al[3] = Alo[base + 8 * LDS_S + 4];
                #pragma unroll
                for (int ni = 0; ni < 4; ni++) {
                    mma_tf32(acc[mi][ni], ah, bl[ni]);
                    mma_tf32(acc[mi][ni], al, bh[ni]);
                    mma_tf32(acc[mi][ni], ah, bh[ni]);
                }
            }
        }
        __syncthreads();
    }

    float* Cb = C + (size_t)bt * strideC;
    if (EPI == 2) {
        #pragma unroll
        for (int mi = 0; mi < 4; mi++) {
            const int gr = m0 + warp_m * 64 + mi * 16 + l4;
            #pragma unroll
            for (int ni = 0; ni < 4; ni++) {
                const int gc = n0 + warp_n * 32 + ni * 8 + lm * 2;
                const float b0 = bias[gc], b1 = bias[gc + 1];
                float2 o0 = { acc[mi][ni][0] + b0, acc[mi][ni][1] + b1 };
                float2 o1 = { acc[mi][ni][2] + b0, acc[mi][ni][3] + b1 };
                *reinterpret_cast<float2*>(&Cb[(size_t)gr * ldc + gc]) = o0;
                *reinterpret_cast<float2*>(&Cb[(size_t)(gr + 8) * ldc + gc]) = o1;
            }
        }
    } else {
        #pragma unroll
        for (int mi = 0; mi < 4; mi++) {
            const int gr = m0 + warp_m * 64 + mi * 16 + l4;
            #pragma unroll
            for (int ni = 0; ni < 4; ni++) {
                const int gc = n0 + warp_n * 32 + ni * 8 + lm * 2;
                float2 o0 = { acc[mi][ni][0], acc[mi][ni][1] };
                float2 o1 = { acc[mi][ni][2], acc[mi][ni][3] };
                *reinterpret_cast<float2*>(&Cb[(size_t)gr * ldc + gc]) = o0;
                *reinterpret_cast<float2*>(&Cb[(size_t)(gr + 8) * ldc + gc]) = o1;
            }
        }
    }
}

// ---------------------------------------------------------------------------
// Launch
// ---------------------------------------------------------------------------
extern "C" void kernel_launch(void* const* d_in, const int* in_sizes, int n_in,
                              void* d_out, int out_size) {
    const float* img   = (const float*)d_in[0];
    const float* tac   = (const float*)d_in[1];
    const float* Wq    = (const float*)d_in[2];
    const float* bq    = (const float*)d_in[3];
    const float* Wk    = (const float*)d_in[4];
    const float* bk    = (const float*)d_in[5];
    const float* Wv    = (const float*)d_in[6];
    const float* bv    = (const float*)d_in[7];
    const float* gamma = (const float*)d_in[8];
    float* out = (float*)d_out;

    float* gX;  cudaGetSymbolAddress((void**)&gX,  g_X);
    float* gXT; cudaGetSymbolAddress((void**)&gXT, g_XT);
    float* gQT; cudaGetSymbolAddress((void**)&gQT, g_QT);
    float* gKT; cudaGetSymbolAddress((void**)&gKT, g_KT);
    float* gV;  cudaGetSymbolAddress((void**)&gV,  g_V);
    float* gA;  cudaGetSymbolAddress((void**)&gA,  g_ATT);

    cudaFuncSetAttribute(gemm_async_kernel<0>, cudaFuncAttributeMaxDynamicSharedMemorySize, SMEM_T);
    cudaFuncSetAttribute(gemm_async_kernel<1>, cudaFuncAttributeMaxDynamicSharedMemorySize, SMEM_T);
    cudaFuncSetAttribute(gemm_mma3_kernel<2>,  cudaFuncAttributeMaxDynamicSharedMemorySize, SMEM_T);
    cudaFuncSetAttribute(gemm_mma3_kernel<3>,  cudaFuncAttributeMaxDynamicSharedMemorySize, SMEM_T);

    // 1) fused feature maps
    build_x_kernel <<<dim3((NP + 255) / 256, CF, BT), 256>>>(img, tac);
    build_xt_kernel<<<dim3(CF / 256, NP, BT), 256>>>(img, tac);

    // 2) q, k projections (3xTF32): QT[n][o] = XT[n][:] @ Wq^T + bq
    gemm_mma3_kernel<2><<<dim3(NP / 128, 1, BT), 256, SMEM_T>>>(
        gXT, CF, (size_t)NP * CF,
        Wq, CF, 0,
        CF, bq,
        gQT, CQ, (size_t)NP * CQ);
    gemm_mma3_kernel<2><<<dim3(NP / 128, 1, BT), 256, SMEM_T>>>(
        gXT, CF, (size_t)NP * CF,
        Wk, CF, 0,
        CF, bk,
        gKT, CQ, (size_t)NP * CQ);

    // 3) v projection (tf32, cp.async): V[c][n] = Wv @ XT^T + bv
    gemm_async_kernel<0><<<dim3(CF / 128, NP / 128, BT), 256, SMEM_T>>>(
        Wv, CF, 0,
        gXT, CF, (size_t)NP * CF,
        CF, bv, nullptr, nullptr,
        gV, NP, (size_t)CF * NP);

    // 4) attention scores (3xTF32): S[n][m] = QT[n][:] @ KT[m][:]^T
    gemm_mma3_kernel<3><<<dim3(NP / 128, NP / 128, BT), 256, SMEM_T>>>(
        gQT, CQ, (size_t)NP * CQ,
        gKT, CQ, (size_t)NP * CQ,
        CQ, nullptr,
        gA, NP, (size_t)NP * NP);

    // 5) softmax
    softmax_kernel<<<dim3(NTOK, BT), 256>>>();

    // 6) out = gamma * (V @ P^T) + X (tf32, cp.async)
    gemm_async_kernel<1><<<dim3(CF / 128, NP / 128, BT), 256, SMEM_T>>>(
        gV, NP, (size_t)CF * NP,
        gA, NP, (size_t)NP * NP,
        NP, nullptr, gamma, gX,
        out, NTOK, (size_t)CF * NTOK);
}

// round 8
// speedup vs baseline: 1.2430x; 1.0186x over previous
#include <cuda_runtime.h>
#include <cstdint>

// ---------------------------------------------------------------------------
// Shapes
// ---------------------------------------------------------------------------
#define BT   12
#define CF   1024
#define CQ   128
#define NTOK 2401
#define NP   2432
#define HF   49

// ---------------------------------------------------------------------------
// Scratch
// ---------------------------------------------------------------------------
__device__ float g_X  [(size_t)BT * CF * NP];   // [bt][c][n]
__device__ float g_XT [(size_t)BT * NP * CF];   // [bt][n][c]
__device__ float g_QT [(size_t)BT * NP * CQ];   // [bt][n][o]
__device__ float g_KT [(size_t)BT * NP * CQ];   // [bt][m][o]
__device__ float g_V  [(size_t)BT * CF * NP];   // [bt][c][n]
__device__ float g_ATT[(size_t)BT * NP * NP];   // [bt][n][m]

__device__ __forceinline__ uint32_t f2tf(float f) {
    uint32_t u; asm("cvt.rna.tf32.f32 %0, %1;" : "=r"(u) : "f"(f)); return u;
}
__device__ __forceinline__ uint32_t u2tf(uint32_t x) {
    uint32_t u; asm("cvt.rna.tf32.f32 %0, %1;" : "=r"(u) : "f"(__uint_as_float(x))); return u;
}
__device__ __forceinline__ uint32_t smem_u32(const void* p) {
    uint32_t a;
    asm("{ .reg .u64 t; cvta.to.shared.u64 t, %1; cvt.u32.u64 %0, t; }" : "=r"(a) : "l"(p));
    return a;
}

__device__ __forceinline__ void mma_tf32(float c[4], const uint32_t a[4], const uint32_t b[2]) {
    asm volatile(
        "mma.sync.aligned.m16n8k8.row.col.f32.tf32.tf32.f32 "
        "{%0,%1,%2,%3}, {%4,%5,%6,%7}, {%8,%9}, {%0,%1,%2,%3};"
        : "+f"(c[0]), "+f"(c[1]), "+f"(c[2]), "+f"(c[3])
        : "r"(a[0]), "r"(a[1]), "r"(a[2]), "r"(a[3]), "r"(b[0]), "r"(b[1]));
}

#define CP_ASYNC16(dst_u32, src_ptr) \
    asm volatile("cp.async.cg.shared.global [%0], [%1], 16;" :: "r"(dst_u32), "l"(src_ptr) : "memory")
#define CP_COMMIT() asm volatile("cp.async.commit_group;" ::: "memory")
#define CP_WAIT0()  asm volatile("cp.async.wait_group 0;" ::: "memory")
#define CP_WAIT1()  asm volatile("cp.async.wait_group 1;" ::: "memory")

// ---------------------------------------------------------------------------
// 1a) X[bt][c][n]  (zero-padded n)
// ---------------------------------------------------------------------------
__global__ void build_x_kernel(const float* __restrict__ img,
                               const float* __restrict__ tac) {
    int n = blockIdx.x * 256 + threadIdx.x;
    int c = blockIdx.y, bt = blockIdx.z;
    if (n >= NP) return;
    float v = 0.0f;
    if (n < NTOK) {
        int i = n / HF, j = n % HF;
        v = (c < 512)
            ? tac[(((size_t)bt * 512 + c) * 7 + (i / 7)) * 7 + (j / 7)]
            : img[(((size_t)bt * 512 + (c - 512)) * 7 + (i % 7)) * 7 + (j % 7)];
    }
    g_X[((size_t)bt * CF + c) * NP + n] = v;
}

// ---------------------------------------------------------------------------
// 1b) XT[bt][n][c]  (zero rows for n >= NTOK)
// ---------------------------------------------------------------------------
__global__ void build_xt_kernel(const float* __restrict__ img,
                                const float* __restrict__ tac) {
    int c = blockIdx.x * 256 + threadIdx.x;
    int n = blockIdx.y, bt = blockIdx.z;
    if (c >= CF) return;
    float v = 0.0f;
    if (n < NTOK) {
        int i = n / HF, j = n % HF;
        v = (c < 512)
            ? tac[(((size_t)bt * 512 + c) * 7 + (i / 7)) * 7 + (j / 7)]
            : img[(((size_t)bt * 512 + (c - 512)) * 7 + (i % 7)) * 7 + (j % 7)];
    }
    g_XT[((size_t)bt * NP + n) * CF + c] = v;
}

// ---------------------------------------------------------------------------
// 2) row softmax (m < 2401), zero padding columns
// ---------------------------------------------------------------------------
__global__ __launch_bounds__(256)
void softmax_kernel() {
    __shared__ float row[NTOK];
    __shared__ float red[256];
    const int n = blockIdx.x, bt = blockIdx.y;
    float* base = g_ATT + ((size_t)bt * NP + n) * NP;
    const int t = threadIdx.x;

    float mx = -1e30f;
    for (int m = t; m < NTOK; m += 256) { float v = base[m]; row[m] = v; mx = fmaxf(mx, v); }
    red[t] = mx; __syncthreads();
    for (int s = 128; s > 0; s >>= 1) { if (t < s) red[t] = fmaxf(red[t], red[t + s]); __syncthreads(); }
    mx = red[0]; __syncthreads();

    float sum = 0.0f;
    for (int m = t; m < NTOK; m += 256) { float e = __expf(row[m] - mx); row[m] = e; sum += e; }
    red[t] = sum; __syncthreads();
    for (int s = 128; s > 0; s >>= 1) { if (t < s) red[t] += red[t + s]; __syncthreads(); }
    float inv = 1.0f / red[0];

    for (int m = t; m < NTOK; m += 256) base[m] = row[m] * inv;
    for (int m = NTOK + t; m < NP; m += 256) base[m] = 0.0f;
}

// ---------------------------------------------------------------------------
// Shared tiling constants (stride-36 layout, conflict-free scalar LDS)
// ---------------------------------------------------------------------------
#define LDS_S 36
#define TILEW (128 * LDS_S)            // words per 128x32 tile
#define SMEM_T (4 * TILEW * 4)         // 73728 B: raw A0,B0,A1,B1 double buffer

// ---------------------------------------------------------------------------
// 3) SPLIT=1 tf32 GEMM, cp.async double-buffered, 2 CTAs/SM.
//    C[M,N] = A[M,K] @ B[N,K]^T (both K-major). Raw fp32 staged in smem;
//    consumer applies cvt.rna.tf32 on fragments.
//    EPI 0: C = acc + bias[row]
//    EPI 1: C = gamma*acc + X[row][col], col<NTOK
// ---------------------------------------------------------------------------
template <int EPI>
__global__ __launch_bounds__(256, 2)
void gemm_async_kernel(const float* __restrict__ A, int lda, size_t strideA,
                       const float* __restrict__ B, int ldb, size_t strideB,
                       int K,
                       const float* __restrict__ bias,
                       const float* __restrict__ gamma,
                       const float* __restrict__ Xres,
                       float* __restrict__ C, int ldc, size_t strideC) {
    extern __shared__ uint32_t sm[];
    const uint32_t smem_base = smem_u32(sm);

    const int bt = blockIdx.z;
    const int m0 = blockIdx.x * 128;
    const int n0 = blockIdx.y * 128;
    const float* Ab = A + (size_t)bt * strideA + (size_t)m0 * lda;
    const float* Bb = B + (size_t)bt * strideB + (size_t)n0 * ldb;

    const int t = threadIdx.x;
    const int wid = t >> 5, lane = t & 31;
    const int warp_m = wid & 1, warp_n = wid >> 1;
    const int l4 = lane >> 2, lm = lane & 3;

    const int prow = t >> 1;
    const int pcol = (t & 1) * 16;
    const float* aRow = Ab + (size_t)prow * lda + pcol;
    const float* bRow = Bb + (size_t)prow * ldb + pcol;
    const uint32_t sA0 = smem_base + (prow * LDS_S + pcol) * 4;
    const uint32_t sB0 = sA0 + TILEW * 4;

    float acc[4][4][4];
    #pragma unroll
    for (int mi = 0; mi < 4; mi++)
        #pragma unroll
        for (int ni = 0; ni < 4; ni++)
            #pragma unroll
            for (int r = 0; r < 4; r++) acc[mi][ni][r] = 0.0f;

    const int NCH = K / 32;

    #pragma unroll
    for (int q = 0; q < 4; q++) {
        CP_ASYNC16(sA0 + q * 16, aRow + q * 4);
        CP_ASYNC16(sB0 + q * 16, bRow + q * 4);
    }
    CP_COMMIT();

    for (int ch = 0; ch < NCH; ch++) {
        const int buf = ch & 1;
        if (ch + 1 < NCH) {
            const int k1 = (ch + 1) * 32;
            const uint32_t dA = sA0 + (buf ^ 1) * (2 * TILEW * 4);
            const uint32_t dB = sB0 + (buf ^ 1) * (2 * TILEW * 4);
            #pragma unroll
            for (int q = 0; q < 4; q++) {
                CP_ASYNC16(dA + q * 16, aRow + k1 + q * 4);
                CP_ASYNC16(dB + q * 16, bRow + k1 + q * 4);
            }
            CP_COMMIT();
            CP_WAIT1();
        } else {
            CP_WAIT0();
        }
        __syncthreads();

        const uint32_t* as = sm + buf * 2 * TILEW;
        const uint32_t* bs = as + TILEW;
        #pragma unroll
        for (int g = 0; g < 4; g++) {
            const int kk = g * 8;
            uint32_t b[4][2];
            #pragma unroll
            for (int ni = 0; ni < 4; ni++) {
                const int base = (warp_n * 32 + ni * 8 + l4) * LDS_S + kk + lm;
                b[ni][0] = u2tf(bs[base]);
                b[ni][1] = u2tf(bs[base + 4]);
            }
            #pragma unroll
            for (int mi = 0; mi < 4; mi++) {
                const int base = (warp_m * 64 + mi * 16 + l4) * LDS_S + kk + lm;
                uint32_t a[4];
                a[0] = u2tf(as[base]);
                a[1] = u2tf(as[base + 8 * LDS_S]);
                a[2] = u2tf(as[base + 4]);
                a[3] = u2tf(as[base + 8 * LDS_S + 4]);
                #pragma unroll
                for (int ni = 0; ni < 4; ni++) mma_tf32(acc[mi][ni], a, b[ni]);
            }
        }
        __syncthreads();
    }

    float* Cb = C + (size_t)bt * strideC;
    if (EPI == 0) {
        #pragma unroll
        for (int mi = 0; mi < 4; mi++) {
            const int gr = m0 + warp_m * 64 + mi * 16 + l4;
            const float bv0 = bias[gr], bv8 = bias[gr + 8];
            #pragma unroll
            for (int ni = 0; ni < 4; ni++) {
                const int gc = n0 + warp_n * 32 + ni * 8 + lm * 2;
                float2 o0 = { acc[mi][ni][0] + bv0, acc[mi][ni][1] + bv0 };
                float2 o1 = { acc[mi][ni][2] + bv8, acc[mi][ni][3] + bv8 };
                *reinterpret_cast<float2*>(&Cb[(size_t)gr * ldc + gc]) = o0;
                *reinterpret_cast<float2*>(&Cb[(size_t)(gr + 8) * ldc + gc]) = o1;
            }
        }
    } else {
        const float g = __ldg(gamma);
        const float* Xb = Xres + (size_t)bt * CF * NP;
        #pragma unroll
        for (int mi = 0; mi < 4; mi++) {
            const int gr = m0 + warp_m * 64 + mi * 16 + l4;
            #pragma unroll
            for (int ni = 0; ni < 4; ni++) {
                const int gc = n0 + warp_n * 32 + ni * 8 + lm * 2;
                if (gc < NTOK)
                    Cb[(size_t)gr * ldc + gc] = g * acc[mi][ni][0] + Xb[(size_t)gr * NP + gc];
                if (gc + 1 < NTOK)
                    Cb[(size_t)gr * ldc + gc + 1] = g * acc[mi][ni][1] + Xb[(size_t)gr * NP + gc + 1];
                if (gc < NTOK)
                    Cb[(size_t)(gr + 8) * ldc + gc] = g * acc[mi][ni][2] + Xb[(size_t)(gr + 8) * NP + gc];
                if (gc + 1 < NTOK)
                    Cb[(size_t)(gr + 8) * ldc + gc + 1] = g * acc[mi][ni][3] + Xb[(size_t)(gr + 8) * NP + gc + 1];
            }
        }
    }
}

// ---------------------------------------------------------------------------
// 4) SPLIT=3 (3xTF32) GEMM, cp.async double-buffered raw staging,
//    hi/lo split on consume, 2 CTAs/SM.
//    EPI 2: fused q/k projection (blockIdx.y selects B/bias/C), C = acc + bias[col]
//    EPI 3: C = acc (raw scores)
// ---------------------------------------------------------------------------
template <int EPI>
__global__ __launch_bounds__(256, 2)
void gemm_async3_kernel(const float* __restrict__ A, int lda, size_t strideA,
                        const float* __restrict__ B, int ldb, size_t strideB,
                        const float* __restrict__ B2,
                        int K,
                        const float* __restrict__ bias,
                        const float* __restrict__ bias2,
                        float* __restrict__ C, int ldc, size_t strideC,
                        float* __restrict__ C2) {
    extern __shared__ uint32_t sm[];
    const uint32_t smem_base = smem_u32(sm);

    const int bt = blockIdx.z;
    const int m0 = blockIdx.x * 128;
    int n0;
    const float* Bsel;
    const float* biassel;
    float* Csel;
    if (EPI == 2) {
        n0 = 0;
        const bool alt = (blockIdx.y != 0);
        Bsel = alt ? B2 : B;
        biassel = alt ? bias2 : bias;
        Csel = alt ? C2 : C;
    } else {
        n0 = blockIdx.y * 128;
        Bsel = B; biassel = bias; Csel = C;
    }

    const float* Ab = A + (size_t)bt * strideA + (size_t)m0 * lda;
    const float* Bb = Bsel + (size_t)bt * strideB + (size_t)n0 * ldb;

    const int t = threadIdx.x;
    const int wid = t >> 5, lane = t & 31;
    const int warp_m = wid & 1, warp_n = wid >> 1;
    const int l4 = lane >> 2, lm = lane & 3;

    const int prow = t >> 1;
    const int pcol = (t & 1) * 16;
    const float* aRow = Ab + (size_t)prow * lda + pcol;
    const float* bRow = Bb + (size_t)prow * ldb + pcol;
    const uint32_t sA0 = smem_base + (prow * LDS_S + pcol) * 4;
    const uint32_t sB0 = sA0 + TILEW * 4;

    float acc[4][4][4];
    #pragma unroll
    for (int mi = 0; mi < 4; mi++)
        #pragma unroll
        for (int ni = 0; ni < 4; ni++)
            #pragma unroll
            for (int r = 0; r < 4; r++) acc[mi][ni][r] = 0.0f;

    const int NCH = K / 32;

    #pragma unroll
    for (int q = 0; q < 4; q++) {
        CP_ASYNC16(sA0 + q * 16, aRow + q * 4);
        CP_ASYNC16(sB0 + q * 16, bRow + q * 4);
    }
    CP_COMMIT();

    for (int ch = 0; ch < NCH; ch++) {
        const int buf = ch & 1;
        if (ch + 1 < NCH) {
            const int k1 = (ch + 1) * 32;
            const uint32_t dA = sA0 + (buf ^ 1) * (2 * TILEW * 4);
            const uint32_t dB = sB0 + (buf ^ 1) * (2 * TILEW * 4);
            #pragma unroll
            for (int q = 0; q < 4; q++) {
                CP_ASYNC16(dA + q * 16, aRow + k1 + q * 4);
                CP_ASYNC16(dB + q * 16, bRow + k1 + q * 4);
            }
            CP_COMMIT();
            CP_WAIT1();
        } else {
            CP_WAIT0();
        }
        __syncthreads();

        const uint32_t* as = sm + buf * 2 * TILEW;
        const uint32_t* bs = as + TILEW;
        #pragma unroll
        for (int g = 0; g < 4; g++) {
            const int kk = g * 8;
            uint32_t bh[4][2], bl[4][2];
            #pragma unroll
            for (int ni = 0; ni < 4; ni++) {
                const int base = (warp_n * 32 + ni * 8 + l4) * LDS_S + kk + lm;
                const uint32_t r0 = bs[base], r1 = bs[base + 4];
                bh[ni][0] = u2tf(r0);
                bl[ni][0] = f2tf(__uint_as_float(r0) - __uint_as_float(bh[ni][0]));
                bh[ni][1] = u2tf(r1);
                bl[ni][1] = f2tf(__uint_as_float(r1) - __uint_as_float(bh[ni][1]));
            }
            #pragma unroll
            for (int mi = 0; mi < 4; mi++) {
                const int base = (warp_m * 64 + mi * 16 + l4) * LDS_S + kk + lm;
                uint32_t ar[4];
                ar[0] = as[base];
                ar[1] = as[base + 8 * LDS_S];
                ar[2] = as[base + 4];
                ar[3] = as[base + 8 * LDS_S + 4];
                uint32_t ah[4], al[4];
                #pragma unroll
                for (int r = 0; r < 4; r++) {
                    ah[r] = u2tf(ar[r]);
                    al[r] = f2tf(__uint_as_float(ar[r]) - __uint_as_float(ah[r]));
                }
                #pragma unroll
                for (int ni = 0; ni < 4; ni++) {
                    mma_tf32(acc[mi][ni], ah, bl[ni]);
                    mma_tf32(acc[mi][ni], al, bh[ni]);
                    mma_tf32(acc[mi][ni], ah, bh[ni]);
                }
            }
        }
        __syncthreads();
    }

    float* Cb = Csel + (size_t)bt * strideC;
    if (EPI == 2) {
        #pragma unroll
        for (int mi = 0; mi < 4; mi++) {
            const int gr = m0 + warp_m * 64 + mi * 16 + l4;
            #pragma unroll
            for (int ni = 0; ni < 4; ni++) {
                const int gc = n0 + warp_n * 32 + ni * 8 + lm * 2;
                const float b0 = biassel[gc], b1 = biassel[gc + 1];
                float2 o0 = { acc[mi][ni][0] + b0, acc[mi][ni][1] + b1 };
                float2 o1 = { acc[mi][ni][2] + b0, acc[mi][ni][3] + b1 };
                *reinterpret_cast<float2*>(&Cb[(size_t)gr * ldc + gc]) = o0;
                *reinterpret_cast<float2*>(&Cb[(size_t)(gr + 8) * ldc + gc]) = o1;
            }
        }
    } else {
        #pragma unroll
        for (int mi = 0; mi < 4; mi++) {
            const int gr = m0 + warp_m * 64 + mi * 16 + l4;
            #pragma unroll
            for (int ni = 0; ni < 4; ni++) {
                const int gc = n0 + warp_n * 32 + ni * 8 + lm * 2;
                float2 o0 = { acc[mi][ni][0], acc[mi][ni][1] };
                float2 o1 = { acc[mi][ni][2], acc[mi][ni][3] };
                *reinterpret_cast<float2*>(&Cb[(size_t)gr * ldc + gc]) = o0;
                *reinterpret_cast<float2*>(&Cb[(size_t)(gr + 8) * ldc + gc]) = o1;
            }
        }
    }
}

// ---------------------------------------------------------------------------
// Launch
// ---------------------------------------------------------------------------
extern "C" void kernel_launch(void* const* d_in, const int* in_sizes, int n_in,
                              void* d_out, int out_size) {
    const float* img   = (const float*)d_in[0];
    const float* tac   = (const float*)d_in[1];
    const float* Wq    = (const float*)d_in[2];
    const float* bq    = (const float*)d_in[3];
    const float* Wk    = (const float*)d_in[4];
    const float* bk    = (const float*)d_in[5];
    const float* Wv    = (const float*)d_in[6];
    const float* bv    = (const float*)d_in[7];
    const float* gamma = (const float*)d_in[8];
    float* out = (float*)d_out;

    float* gX;  cudaGetSymbolAddress((void**)&gX,  g_X);
    float* gXT; cudaGetSymbolAddress((void**)&gXT, g_XT);
    float* gQT; cudaGetSymbolAddress((void**)&gQT, g_QT);
    float* gKT; cudaGetSymbolAddress((void**)&gKT, g_KT);
    float* gV;  cudaGetSymbolAddress((void**)&gV,  g_V);
    float* gA;  cudaGetSymbolAddress((void**)&gA,  g_ATT);

    cudaFuncSetAttribute(gemm_async_kernel<0>,  cudaFuncAttributeMaxDynamicSharedMemorySize, SMEM_T);
    cudaFuncSetAttribute(gemm_async_kernel<1>,  cudaFuncAttributeMaxDynamicSharedMemorySize, SMEM_T);
    cudaFuncSetAttribute(gemm_async3_kernel<2>, cudaFuncAttributeMaxDynamicSharedMemorySize, SMEM_T);
    cudaFuncSetAttribute(gemm_async3_kernel<3>, cudaFuncAttributeMaxDynamicSharedMemorySize, SMEM_T);

    // 1) fused feature maps
    build_x_kernel <<<dim3((NP + 255) / 256, CF, BT), 256>>>(img, tac);
    build_xt_kernel<<<dim3(CF / 256, NP, BT), 256>>>(img, tac);

    // 2) fused q+k projections (3xTF32, cp.async): QT/KT[n][o] = XT[n][:] @ W^T + b
    gemm_async3_kernel<2><<<dim3(NP / 128, 2, BT), 256, SMEM_T>>>(
        gXT, CF, (size_t)NP * CF,
        Wq, CF, 0, Wk,
        CF, bq, bk,
        gQT, CQ, (size_t)NP * CQ, gKT);

    // 3) v projection (tf32, cp.async): V[c][n] = Wv @ XT^T + bv
    gemm_async_kernel<0><<<dim3(CF / 128, NP / 128, BT), 256, SMEM_T>>>(
        Wv, CF, 0,
        gXT, CF, (size_t)NP * CF,
        CF, bv, nullptr, nullptr,
        gV, NP, (size_t)CF * NP);

    // 4) attention scores (3xTF32, cp.async): S[n][m] = QT[n][:] @ KT[m][:]^T
    gemm_async3_kernel<3><<<dim3(NP / 128, NP / 128, BT), 256, SMEM_T>>>(
        gQT, CQ, (size_t)NP * CQ,
        gKT, CQ, (size_t)NP * CQ, nullptr,
        CQ, nullptr, nullptr,
        gA, NP, (size_t)NP * NP, nullptr);

    // 5) softmax
    softmax_kernel<<<dim3(NTOK, BT), 256>>>();

    // 6) out = gamma * (V @ P^T) + X (tf32, cp.async)
    gemm_async_kernel<1><<<dim3(CF / 128, NP / 128, BT), 256, SMEM_T>>>(
        gV, NP, (size_t)CF * NP,
        gA, NP, (size_t)NP * NP,
        NP, nullptr, gamma, gX,
        out, NTOK, (size_t)CF * NTOK);
}